// round 17
// baseline (speedup 1.0000x reference)
#include <cuda_runtime.h>
#include <cuda_fp16.h>
#include <math.h>
#include <stdint.h>

// ---------------------------------------------------------------------------
// GCGRU encoder-decoder. FP16 legacy tensor cores (mma.m16n8k16, fp32 accum),
// ldmatrix loads, 2-stage cp.async GEMMs, fused concat epilogues, cross-layer
// Y reuse, hoisted encoder x-products.
// R17: layer-1 gate gemm1 MIRRORS its x-region stores straight into Y0's
// h-region (kills all h-copy passes); k_gemm2p writes X0 x-cols (kills the
// decoder prep launches).
// ---------------------------------------------------------------------------

#define N_    1024
#define B_    64
#define T_    12
#define HOR_  12
#define C_    2
#define H_    64
#define K_    6

#define NBH_  (N_ * B_ * H_)
#define M_    (N_ * B_)

#define DINR0 66
#define DINP0 80
#define DINR1 128
#define DINP1 128
#define LDP0  (DINP0 * B_)   // 5120
#define LDP1  (DINP1 * B_)   // 8192
#define LDE   (T_ * C_ * B_) // 1536

// ------------------------- scratch (device globals) -------------------------
__device__ float  g_xT[T_ * N_ * B_ * C_];
__device__ float  g_seq[T_ * N_ * B_ * H_];
__device__ float  g_hA[NBH_];
__device__ float  g_hB[NBH_];
__device__ __half g_X0[N_ * LDP0];
__device__ __half g_X1[N_ * LDP1];
__device__ __half g_Y0[4ll * N_ * LDP0];
__device__ __half g_Y1[4ll * N_ * LDP1];
__device__ __half g_Xenc[N_ * LDE];
__device__ __half g_Yx0[4ll * N_ * LDE];
__device__ float  g_zr[(size_t)M_ * H_];
__device__ float  g_y[M_ * C_];
__device__ __half g_Gt[4 * N_ * N_];
__device__ __half g_Wp[479232];

// ------------------------------ helpers -------------------------------------
__device__ __forceinline__ void mma_f16(float* c, const uint32_t* a,
                                        const uint32_t* b) {
    asm volatile(
        "mma.sync.aligned.m16n8k16.row.col.f32.f16.f16.f32 "
        "{%0,%1,%2,%3}, {%4,%5,%6,%7}, {%8,%9}, {%0,%1,%2,%3};\n"
        : "+f"(c[0]), "+f"(c[1]), "+f"(c[2]), "+f"(c[3])
        : "r"(a[0]), "r"(a[1]), "r"(a[2]), "r"(a[3]), "r"(b[0]), "r"(b[1]));
}

__device__ __forceinline__ void ldmx4(uint32_t* r, const void* p) {
    uint32_t a = (uint32_t)__cvta_generic_to_shared(p);
    asm volatile("ldmatrix.sync.aligned.m8n8.x4.shared.b16 {%0,%1,%2,%3}, [%4];"
                 : "=r"(r[0]), "=r"(r[1]), "=r"(r[2]), "=r"(r[3]) : "r"(a));
}
__device__ __forceinline__ void ldmx4t(uint32_t* r, const void* p) {
    uint32_t a = (uint32_t)__cvta_generic_to_shared(p);
    asm volatile("ldmatrix.sync.aligned.m8n8.x4.trans.shared.b16 {%0,%1,%2,%3}, [%4];"
                 : "=r"(r[0]), "=r"(r[1]), "=r"(r[2]), "=r"(r[3]) : "r"(a));
}

__device__ __forceinline__ void cp16(void* dst, const void* src) {
    uint32_t d = (uint32_t)__cvta_generic_to_shared(dst);
    asm volatile("cp.async.ca.shared.global [%0], [%1], 16;\n"
                 :: "r"(d), "l"(src));
}
__device__ __forceinline__ void cp16cg(void* dst, const void* src) {
    uint32_t d = (uint32_t)__cvta_generic_to_shared(dst);
    asm volatile("cp.async.cg.shared.global [%0], [%1], 16;\n"
                 :: "r"(d), "l"(src));
}
__device__ __forceinline__ void cp_commit() {
    asm volatile("cp.async.commit_group;\n");
}
template <int n>
__device__ __forceinline__ void cp_wait() {
    asm volatile("cp.async.wait_group %0;\n" :: "n"(n));
}

// ------------------------------ prep kernels --------------------------------

__global__ void k_prep_G(const float* __restrict__ G) {
    int idx = blockIdx.x * blockDim.x + threadIdx.x;
    if (idx >= 4 * N_ * N_) return;
    int s = idx / (N_ * N_);
    int r = idx - s * (N_ * N_);
    int kidx = s + 1 + (s >> 1);   // {1,2,4,5}
    g_Gt[idx] = __float2half_rn(G[(size_t)kidx * N_ * N_ + r]);
}

__global__ void k_prep_W(const float* __restrict__ src, __half* __restrict__ dst,
                         int din_r, int din_p, int outd) {
    int idx = blockIdx.x * blockDim.x + threadIdx.x;
    int total = K_ * din_p * outd;
    if (idx >= total) return;
    int o = idx % outd;
    int row = idx / outd;
    int k = row / din_p;
    int f = row - k * din_p;
    dst[idx] = (f < din_r) ? __float2half_rn(src[(size_t)(k * din_r + f) * outd + o])
                           : __float2half_rn(0.f);
}

// ------------------------------ data movement -------------------------------

// x (B,T,N,C) -> g_xT (T,N,B,C)
__global__ void k_transpose_x(const float* __restrict__ x) {
    int idx = blockIdx.x * blockDim.x + threadIdx.x;
    const int total = B_ * T_ * N_ * C_;
    if (idx >= total) return;
    int c = idx % C_;
    int i = (idx / C_) % N_;
    int t = (idx / (C_ * N_)) % T_;
    int b = idx / (C_ * N_ * T_);
    g_xT[(((size_t)t * N_ + i) * B_ + b) * C_ + c] = x[idx];
}

// Build Xenc[i][t*128 + f*64 + b] for all t.
__global__ void k_concat_xenc() {
    int idx = blockIdx.x * blockDim.x + threadIdx.x;
    const int total = N_ * T_ * C_ * B_;
    if (idx >= total) return;
    int b = idx & 63;
    int f = (idx >> 6) & 1;
    int t = (idx >> 7) % T_;
    int i = idx / (128 * T_);
    float v = g_xT[(((size_t)t * N_ + i) * B_ + b) * C_ + f];
    g_Xenc[(size_t)i * LDE + t * 128 + f * 64 + b] = __float2half_rn(v);
}

// Encoder layer-0 prep: xprod copy + x-concat (h-copy now mirrored at source).
#define P0E_XPRODN (4 * N_ * 16)
#define P0E_XCONCN (N_ * C_ * B_)
__global__ void k_prep0e(int t, const float* __restrict__ xin,
                         __half* __restrict__ Yp0, __half* __restrict__ Xp) {
    int idx = blockIdx.x * blockDim.x + threadIdx.x;
    if (idx < P0E_XPRODN) {
        int u = idx & 15;
        int i = (idx >> 4) & (N_ - 1);
        int s = idx >> 14;
        size_t so = ((size_t)s * N_ + i) * LDE + t * 128 + u * 8;
        size_t dofs = ((size_t)s * N_ + i) * LDP0 + u * 8;
        *(uint4*)&Yp0[dofs] = *(const uint4*)&g_Yx0[so];
        return;
    }
    int e = idx - P0E_XPRODN;
    if (e >= P0E_XCONCN) return;
    int b = e & 63;
    int f = (e >> 6) & 1;
    int i = e >> 7;
    int m = i * B_ + b;
    Xp[((size_t)i * DINP0 + f) * B_ + b] =
        __float2half_rn(xin[(size_t)m * C_ + f]);
}

// Decoder t=0 x-concat only (y = 0).
__global__ void k_conc0(const float* __restrict__ xin, __half* __restrict__ X) {
    int idx = blockIdx.x * blockDim.x + threadIdx.x;
    if (idx >= N_ * C_ * B_) return;
    int b = idx & 63;
    int f = (idx >> 6) & 1;
    int i = idx >> 7;
    int m = i * B_ + b;
    X[((size_t)i * DINP0 + f) * B_ + b] =
        __float2half_rn(xin[(size_t)m * C_ + f]);
}

// ------------------------------ stage-1 GEMM --------------------------------
// Y[s] = G[s] @ X over columns [col_off, col_off + gridX*128).
// Optional Ymir: mirror stores of xcol<4096 into Y0 h-region (+128, LDP0).
#define G1_A_ROWS 128
#define G1_A_LD   72
#define G1_B_ROWS 64
#define G1_B_LD   136
#define G1_A_BYTES (G1_A_ROWS * G1_A_LD * 2)
#define G1_B_BYTES (G1_B_ROWS * G1_B_LD * 2)
#define G1_SMEM (2 * (G1_A_BYTES + G1_B_BYTES))   // 71680

__global__ __launch_bounds__(256)
void k_gemm1(const __half* __restrict__ Gt, const __half* __restrict__ X,
             __half* __restrict__ Y, int col_off, int ldp,
             __half* __restrict__ Ymir) {
    extern __shared__ __align__(16) char dsm[];
    __half (*As)[G1_A_ROWS][G1_A_LD] =
        reinterpret_cast<__half(*)[G1_A_ROWS][G1_A_LD]>(dsm);
    __half (*Bs)[G1_B_ROWS][G1_B_LD] =
        reinterpret_cast<__half(*)[G1_B_ROWS][G1_B_LD]>(dsm + 2 * G1_A_BYTES);

    const int s = blockIdx.z;
    const __half* A = Gt + (size_t)s * N_ * N_;
    const int m0 = blockIdx.y * 128;
    const int n0 = col_off + blockIdx.x * 128;
    const int tid = threadIdx.x;
    const int lane = tid & 31;
    const int warp = tid >> 5;
    const int wm = (warp & 3) * 32;
    const int wn = (warp >> 2) * 64;
    const int gq = lane >> 2;
    const int t4 = lane & 3;

    float acc[2][8][4];
#pragma unroll
    for (int i = 0; i < 2; i++)
#pragma unroll
        for (int j = 0; j < 8; j++)
#pragma unroll
            for (int l = 0; l < 4; l++) acc[i][j][l] = 0.f;

    auto load_stage = [&](int buf, int kk0) {
#pragma unroll
        for (int i = 0; i < 4; i++) {
            int idx = tid + i * 256;
            int row = idx >> 3;
            int seg = (idx & 7) << 3;
            cp16cg(&As[buf][row][seg], A + (size_t)(m0 + row) * N_ + kk0 + seg);
        }
#pragma unroll
        for (int i = 0; i < 4; i++) {
            int idx = tid + i * 256;
            int r = idx >> 4;
            int seg = (idx & 15) << 3;
            cp16(&Bs[buf][r][seg], X + (size_t)(kk0 + r) * ldp + n0 + seg);
        }
    };

    load_stage(0, 0);
    cp_commit();

    const int KSTEPS = N_ / 64;
    for (int kt = 0; kt < KSTEPS; kt++) {
        int buf = kt & 1;
        if (kt + 1 < KSTEPS) {
            load_stage(buf ^ 1, (kt + 1) * 64);
            cp_commit();
            cp_wait<1>();
        } else {
            cp_wait<0>();
        }
        __syncthreads();

#pragma unroll
        for (int ks = 0; ks < 4; ks++) {
            const int kb = ks * 16;
            uint32_t a[2][4], b[8][2];
#pragma unroll
            for (int mt = 0; mt < 2; mt++) {
                ldmx4(a[mt], &As[buf][wm + mt * 16 + (lane & 15)]
                                     [kb + (lane >> 4) * 8]);
            }
#pragma unroll
            for (int p = 0; p < 4; p++) {
                uint32_t r[4];
                ldmx4t(r, &Bs[buf][kb + (lane & 7) + ((lane >> 3) & 1) * 8]
                                  [wn + p * 16 + (lane >> 4) * 8]);
                b[2 * p][0] = r[0]; b[2 * p][1] = r[1];
                b[2 * p + 1][0] = r[2]; b[2 * p + 1][1] = r[3];
            }
#pragma unroll
            for (int mt = 0; mt < 2; mt++)
#pragma unroll
                for (int nt = 0; nt < 8; nt++)
                    mma_f16(acc[mt][nt], a[mt], b[nt]);
        }
        __syncthreads();
    }

#pragma unroll
    for (int mt = 0; mt < 2; mt++) {
        int row = m0 + wm + mt * 16 + gq;
#pragma unroll
        for (int nt = 0; nt < 8; nt++) {
            int xcol = n0 + wn + nt * 8 + t4 * 2;
#pragma unroll
            for (int hh = 0; hh < 2; hh++) {
                int rr = row + hh * 8;
                __half2 v = __floats2half2_rn(acc[mt][nt][hh * 2 + 0],
                                              acc[mt][nt][hh * 2 + 1]);
                *(__half2*)&Y[((size_t)s * N_ + rr) * ldp + xcol] = v;
                if (Ymir && xcol < 4096)
                    *(__half2*)&Ymir[((size_t)s * N_ + rr) * LDP0 + 128 + xcol]
                        = v;
            }
        }
    }
}

// ------------------------- stage-2 gate GEMM (BN=128) ------------------------
__global__ __launch_bounds__(256)
void k_gemm2g(const __half* __restrict__ Xp, const __half* __restrict__ Yp,
              const __half* __restrict__ W, const float* __restrict__ bias,
              int din_p, const float* __restrict__ hprev,
              __half* __restrict__ Xh, int dinx) {
    __shared__ __align__(16) __half Ask[2][32][136];
    __shared__ __align__(16) __half Bs[2][32][136];

    const int m0 = blockIdx.y * 128;
    const int i0 = m0 >> 6;
    const int tid = threadIdx.x;
    const int lane = tid & 31;
    const int warp = tid >> 5;
    const int wm = (warp & 3) * 32;
    const int wn = (warp >> 2) * 64;
    const int gq = lane >> 2;
    const int t4 = lane & 3;
    const int ldp = din_p * B_;

    float acc[2][8][4];
#pragma unroll
    for (int i = 0; i < 2; i++)
#pragma unroll
        for (int j = 0; j < 8; j++)
#pragma unroll
            for (int l = 0; l < 4; l++) acc[i][j][l] = 0.f;

    auto load_stage = [&](int buf, int kt) {
#pragma unroll
        for (int s16 = 0; s16 < 2; s16++) {
            int kk16 = kt * 32 + s16 * 16;
            int k = kk16 / din_p;
            int f0 = kk16 - k * din_p;
            const __half* basep;
            if (k == 0 || k == 3) basep = Xp;
            else basep = Yp + (size_t)((k < 3) ? k - 1 : k - 2) * N_ * ldp;
            int j = tid >> 4;
            int q = tid & 15;
            int node = q >> 3;
            int ch = (q & 7) << 3;
            cp16(&Ask[buf][s16 * 16 + j][node * 64 + ch],
                 basep + ((size_t)(i0 + node) * din_p + f0 + j) * B_ + ch);
        }
        {
            int kk0 = kt * 32;
#pragma unroll
            for (int i = 0; i < 2; i++) {
                int idx = tid + i * 256;
                int r = idx >> 4;
                int ch = (idx & 15) << 3;
                cp16(&Bs[buf][r][ch], W + (size_t)(kk0 + r) * 128 + ch);
            }
        }
    };

    load_stage(0, 0);
    cp_commit();

    const int KSTEPS = (K_ * din_p) >> 5;
    for (int kt = 0; kt < KSTEPS; kt++) {
        int buf = kt & 1;
        if (kt + 1 < KSTEPS) {
            load_stage(buf ^ 1, kt + 1);
            cp_commit();
            cp_wait<1>();
        } else {
            cp_wait<0>();
        }
        __syncthreads();

#pragma unroll
        for (int ks = 0; ks < 2; ks++) {
            const int kb = ks * 16;
            uint32_t a[2][4], b[8][2];
#pragma unroll
            for (int mt = 0; mt < 2; mt++) {
                ldmx4t(a[mt], &Ask[buf][kb + (lane & 7) + ((lane >> 4) & 1) * 8]
                                       [wm + mt * 16 + ((lane >> 3) & 1) * 8]);
            }
#pragma unroll
            for (int p = 0; p < 4; p++) {
                uint32_t r[4];
                ldmx4t(r, &Bs[buf][kb + (lane & 7) + ((lane >> 3) & 1) * 8]
                                  [wn + p * 16 + (lane >> 4) * 8]);
                b[2 * p][0] = r[0]; b[2 * p][1] = r[1];
                b[2 * p + 1][0] = r[2]; b[2 * p + 1][1] = r[3];
            }
#pragma unroll
            for (int mt = 0; mt < 2; mt++)
#pragma unroll
                for (int nt = 0; nt < 8; nt++)
                    mma_f16(acc[mt][nt], a[mt], b[nt]);
        }
        __syncthreads();
    }

#pragma unroll
    for (int mt = 0; mt < 2; mt++) {
        int row = m0 + wm + mt * 16 + gq;
#pragma unroll
        for (int nt = 0; nt < 8; nt++) {
            int nb = wn + nt * 8 + t4 * 2;
#pragma unroll
            for (int hh = 0; hh < 2; hh++) {
                size_t m = (size_t)(row + hh * 8);
#pragma unroll
                for (int cc = 0; cc < 2; cc++) {
                    int n = nb + cc;
                    float v = acc[mt][nt][hh * 2 + cc] + bias[n];
                    float sig = 1.f / (1.f + expf(-v));
                    if (n < H_) {
                        g_zr[m * H_ + n] = sig;
                    } else {
                        int j = n - H_;
                        float hv = hprev ? hprev[m * H_ + j] : 0.f;
                        Xh[((size_t)(m >> 6) * din_p + dinx + j) * B_ +
                           (m & 63)] = __float2half_rn(sig * hv);
                    }
                }
            }
        }
    }
}

// ------------------------- stage-2 update GEMM (BN=64) -----------------------
__global__ __launch_bounds__(256)
void k_gemm2(const __half* __restrict__ Xp, const __half* __restrict__ Yp,
             const __half* __restrict__ W, const float* __restrict__ bias,
             int din_p,
             const float* __restrict__ hprev, float* __restrict__ hout,
             __half* __restrict__ Xh, int dinx, __half* __restrict__ Xx) {
    __shared__ __align__(16) __half Ask[2][32][136];
    __shared__ __align__(16) __half Bs[2][32][72];

    const int m0 = blockIdx.y * 128;
    const int i0 = m0 >> 6;
    const int tid = threadIdx.x;
    const int lane = tid & 31;
    const int warp = tid >> 5;
    const int wm = (warp & 3) * 32;
    const int wn = (warp >> 2) * 32;
    const int gq = lane >> 2;
    const int t4 = lane & 3;
    const int ldp = din_p * B_;

    float acc[2][4][4];
#pragma unroll
    for (int i = 0; i < 2; i++)
#pragma unroll
        for (int j = 0; j < 4; j++)
#pragma unroll
            for (int l = 0; l < 4; l++) acc[i][j][l] = 0.f;

    auto load_stage = [&](int buf, int kt) {
#pragma unroll
        for (int s16 = 0; s16 < 2; s16++) {
            int kk16 = kt * 32 + s16 * 16;
            int k = kk16 / din_p;
            int f0 = kk16 - k * din_p;
            const __half* basep;
            if (k == 0 || k == 3) basep = Xp;
            else basep = Yp + (size_t)((k < 3) ? k - 1 : k - 2) * N_ * ldp;
            int j = tid >> 4;
            int q = tid & 15;
            int node = q >> 3;
            int ch = (q & 7) << 3;
            cp16(&Ask[buf][s16 * 16 + j][node * 64 + ch],
                 basep + ((size_t)(i0 + node) * din_p + f0 + j) * B_ + ch);
        }
        {
            int kk0 = kt * 32;
            int r = tid >> 3;
            int ch = (tid & 7) << 3;
            cp16(&Bs[buf][r][ch], W + (size_t)(kk0 + r) * 64 + ch);
        }
    };

    load_stage(0, 0);
    cp_commit();

    const int KSTEPS = (K_ * din_p) >> 5;
    for (int kt = 0; kt < KSTEPS; kt++) {
        int buf = kt & 1;
        if (kt + 1 < KSTEPS) {
            load_stage(buf ^ 1, kt + 1);
            cp_commit();
            cp_wait<1>();
        } else {
            cp_wait<0>();
        }
        __syncthreads();

#pragma unroll
        for (int ks = 0; ks < 2; ks++) {
            const int kb = ks * 16;
            uint32_t a[2][4], b[4][2];
#pragma unroll
            for (int mt = 0; mt < 2; mt++) {
                ldmx4t(a[mt], &Ask[buf][kb + (lane & 7) + ((lane >> 4) & 1) * 8]
                                       [wm + mt * 16 + ((lane >> 3) & 1) * 8]);
            }
#pragma unroll
            for (int p = 0; p < 2; p++) {
                uint32_t r[4];
                ldmx4t(r, &Bs[buf][kb + (lane & 7) + ((lane >> 3) & 1) * 8]
                                  [wn + p * 16 + (lane >> 4) * 8]);
                b[2 * p][0] = r[0]; b[2 * p][1] = r[1];
                b[2 * p + 1][0] = r[2]; b[2 * p + 1][1] = r[3];
            }
#pragma unroll
            for (int mt = 0; mt < 2; mt++)
#pragma unroll
                for (int nt = 0; nt < 4; nt++)
                    mma_f16(acc[mt][nt], a[mt], b[nt]);
        }
        __syncthreads();
    }

#pragma unroll
    for (int mt = 0; mt < 2; mt++) {
        int row = m0 + wm + mt * 16 + gq;
#pragma unroll
        for (int nt = 0; nt < 4; nt++) {
            int nb = wn + nt * 8 + t4 * 2;
#pragma unroll
            for (int hh = 0; hh < 2; hh++) {
                size_t m = (size_t)(row + hh * 8);
#pragma unroll
                for (int cc = 0; cc < 2; cc++) {
                    int n = nb + cc;
                    float v = acc[mt][nt][hh * 2 + cc] + bias[n];
                    float z = g_zr[m * H_ + n];
                    float hold = hprev ? hprev[m * H_ + n] : 0.f;
                    float hnew = z * tanhf(v) + (1.f - z) * hold;
                    hout[m * H_ + n] = hnew;
                    __half hh16 = __float2half_rn(hnew);
                    Xh[((size_t)(m >> 6) * din_p + dinx + n) * B_ + (m & 63)] =
                        hh16;
                    if (Xx)
                        Xx[((size_t)(m >> 6) * DINP1 + n) * B_ + (m & 63)] =
                            hh16;
                }
            }
        }
    }
}

// --------------- stage-2 update GEMM + fused projection (dec1) ---------------
#define G2P_ASK_B (2 * 32 * 136 * 2)
#define G2P_BS_B  (2 * 32 * 72 * 2)
#define G2P_HS_B  (128 * 65 * 4)
#define G2P_SMEM  (G2P_ASK_B + G2P_BS_B + G2P_HS_B)   // 59904

__global__ __launch_bounds__(256)
void k_gemm2p(const __half* __restrict__ Xp, const __half* __restrict__ Yp,
              const __half* __restrict__ W, const float* __restrict__ bias,
              const float* __restrict__ hprev, float* __restrict__ hout,
              __half* __restrict__ Xh, __half* __restrict__ Xx0,
              const float* __restrict__ projW, const float* __restrict__ projb,
              int t, float* __restrict__ out) {
    extern __shared__ __align__(16) char dsm2[];
    __half (*Ask)[32][136] = reinterpret_cast<__half(*)[32][136]>(dsm2);
    __half (*Bs)[32][72]   = reinterpret_cast<__half(*)[32][72]>(dsm2 + G2P_ASK_B);
    float (*hs)[65]        = reinterpret_cast<float(*)[65]>(dsm2 + G2P_ASK_B +
                                                            G2P_BS_B);
    const int din_p = DINP1, dinx = H_;
    const int m0 = blockIdx.y * 128;
    const int i0 = m0 >> 6;
    const int tid = threadIdx.x;
    const int lane = tid & 31;
    const int warp = tid >> 5;
    const int wm = (warp & 3) * 32;
    const int wn = (warp >> 2) * 32;
    const int gq = lane >> 2;
    const int t4 = lane & 3;
    const int ldp = din_p * B_;

    float acc[2][4][4];
#pragma unroll
    for (int i = 0; i < 2; i++)
#pragma unroll
        for (int j = 0; j < 4; j++)
#pragma unroll
            for (int l = 0; l < 4; l++) acc[i][j][l] = 0.f;

    auto load_stage = [&](int buf, int kt) {
#pragma unroll
        for (int s16 = 0; s16 < 2; s16++) {
            int kk16 = kt * 32 + s16 * 16;
            int k = kk16 / din_p;
            int f0 = kk16 - k * din_p;
            const __half* basep;
            if (k == 0 || k == 3) basep = Xp;
            else basep = Yp + (size_t)((k < 3) ? k - 1 : k - 2) * N_ * ldp;
            int j = tid >> 4;
            int q = tid & 15;
            int node = q >> 3;
            int ch = (q & 7) << 3;
            cp16(&Ask[buf][s16 * 16 + j][node * 64 + ch],
                 basep + ((size_t)(i0 + node) * din_p + f0 + j) * B_ + ch);
        }
        {
            int kk0 = kt * 32;
            int r = tid >> 3;
            int ch = (tid & 7) << 3;
            cp16(&Bs[buf][r][ch], W + (size_t)(kk0 + r) * 64 + ch);
        }
    };

    load_stage(0, 0);
    cp_commit();

    const int KSTEPS = (K_ * din_p) >> 5;   // 24
    for (int kt = 0; kt < KSTEPS; kt++) {
        int buf = kt & 1;
        if (kt + 1 < KSTEPS) {
            load_stage(buf ^ 1, kt + 1);
            cp_commit();
            cp_wait<1>();
        } else {
            cp_wait<0>();
        }
        __syncthreads();

#pragma unroll
        for (int ks = 0; ks < 2; ks++) {
            const int kb = ks * 16;
            uint32_t a[2][4], b[4][2];
#pragma unroll
            for (int mt = 0; mt < 2; mt++) {
                ldmx4t(a[mt], &Ask[buf][kb + (lane & 7) + ((lane >> 4) & 1) * 8]
                                       [wm + mt * 16 + ((lane >> 3) & 1) * 8]);
            }
#pragma unroll
            for (int p = 0; p < 2; p++) {
                uint32_t r[4];
                ldmx4t(r, &Bs[buf][kb + (lane & 7) + ((lane >> 3) & 1) * 8]
                                  [wn + p * 16 + (lane >> 4) * 8]);
                b[2 * p][0] = r[0]; b[2 * p][1] = r[1];
                b[2 * p + 1][0] = r[2]; b[2 * p + 1][1] = r[3];
            }
#pragma unroll
            for (int mt = 0; mt < 2; mt++)
#pragma unroll
                for (int nt = 0; nt < 4; nt++)
                    mma_f16(acc[mt][nt], a[mt], b[nt]);
        }
        __syncthreads();
    }

#pragma unroll
    for (int mt = 0; mt < 2; mt++) {
        int row = m0 + wm + mt * 16 + gq;
#pragma unroll
        for (int nt = 0; nt < 4; nt++) {
            int nb = wn + nt * 8 + t4 * 2;
#pragma unroll
            for (int hh = 0; hh < 2; hh++) {
                size_t m = (size_t)(row + hh * 8);
#pragma unroll
                for (int cc = 0; cc < 2; cc++) {
                    int n = nb + cc;
                    float v = acc[mt][nt][hh * 2 + cc] + bias[n];
                    float z = g_zr[m * H_ + n];
                    float hold = hprev ? hprev[m * H_ + n] : 0.f;
                    float hnew = z * tanhf(v) + (1.f - z) * hold;
                    hout[m * H_ + n] = hnew;
                    Xh[((size_t)(m >> 6) * din_p + dinx + n) * B_ + (m & 63)] =
                        __float2half_rn(hnew);
                    hs[m - m0][n] = hnew;
                }
            }
        }
    }

    __syncthreads();
    // fused projection: writes out, g_y feedback, and X0 x-cols (next dec0)
    if (tid < 128) {
        int m = m0 + tid;
        int i = m >> 6;
        int b = m & 63;
        float a0 = projb[0], a1 = projb[1];
        for (int j = 0; j < H_; j++) {
            float h = hs[tid][j];
            a0 += h * projW[j * 2 + 0];
            a1 += h * projW[j * 2 + 1];
        }
        g_y[(size_t)m * C_ + 0] = a0;
        g_y[(size_t)m * C_ + 1] = a1;
        Xx0[((size_t)i * DINP0 + 0) * B_ + b] = __float2half_rn(a0);
        Xx0[((size_t)i * DINP0 + 1) * B_ + b] = __float2half_rn(a1);
        size_t o = ((((size_t)b * HOR_ + t) * N_) + i) * C_;
        out[o + 0] = a0;
        out[o + 1] = a1;
    }
}

// ------------------------------ host side -----------------------------------

static inline int cdiv(int a, int b) { return (a + b - 1) / b; }

#define OFF_E0G 0
#define OFF_E0U 61440
#define OFF_D0G 92160
#define OFF_D0U 153600
#define OFF_E1G 184320
#define OFF_E1U 282624
#define OFF_D1G 331776
#define OFF_D1U 430080

extern "C" void kernel_launch(void* const* d_in, const int* in_sizes, int n_in,
                              void* d_out, int out_size) {
    (void)in_sizes; (void)n_in; (void)out_size;

    const float* x = (const float*)d_in[0];
    const float* G = (const float*)d_in[1];
    const float* w[16];
    for (int i = 0; i < 16; i++) w[i] = (const float*)d_in[2 + i];
    const float* projW = (const float*)d_in[18];
    const float* projb = (const float*)d_in[19];
    float* out = (float*)d_out;

    cudaFuncSetAttribute(k_gemm1, cudaFuncAttributeMaxDynamicSharedMemorySize,
                         G1_SMEM);
    cudaFuncSetAttribute(k_gemm2p, cudaFuncAttributeMaxDynamicSharedMemorySize,
                         G2P_SMEM);

    float *p_xT, *p_seq, *p_hA, *p_hB, *p_y;
    __half *p_X0, *p_X1, *p_Y0, *p_Y1, *p_Gt, *p_Wp, *p_Xenc, *p_Yx0;
    cudaGetSymbolAddress((void**)&p_xT,   g_xT);
    cudaGetSymbolAddress((void**)&p_seq,  g_seq);
    cudaGetSymbolAddress((void**)&p_hA,   g_hA);
    cudaGetSymbolAddress((void**)&p_hB,   g_hB);
    cudaGetSymbolAddress((void**)&p_y,    g_y);
    cudaGetSymbolAddress((void**)&p_X0,   g_X0);
    cudaGetSymbolAddress((void**)&p_X1,   g_X1);
    cudaGetSymbolAddress((void**)&p_Y0,   g_Y0);
    cudaGetSymbolAddress((void**)&p_Y1,   g_Y1);
    cudaGetSymbolAddress((void**)&p_Gt,   g_Gt);
    cudaGetSymbolAddress((void**)&p_Wp,   g_Wp);
    cudaGetSymbolAddress((void**)&p_Xenc, g_Xenc);
    cudaGetSymbolAddress((void**)&p_Yx0,  g_Yx0);

    // replay-safe zeroing (zero-h regions + pads)
    cudaMemsetAsync(p_X0, 0, (size_t)N_ * LDP0 * sizeof(__half));
    cudaMemsetAsync(p_X1, 0, (size_t)N_ * LDP1 * sizeof(__half));
    cudaMemsetAsync(p_Y0, 0, 4ll * N_ * LDP0 * sizeof(__half));
    cudaMemsetAsync(p_Y1, 0, 4ll * N_ * LDP1 * sizeof(__half));
    cudaMemsetAsync(p_y,  0, (size_t)M_ * C_ * sizeof(float));

    // prep
    k_prep_G<<<cdiv(4 * N_ * N_, 256), 256>>>(G);
    k_transpose_x<<<cdiv(B_ * T_ * N_ * C_, 256), 256>>>(x);
    k_prep_W<<<cdiv(K_ * DINP0 * 128, 256), 256>>>(w[0],  p_Wp + OFF_E0G, DINR0, DINP0, 128);
    k_prep_W<<<cdiv(K_ * DINP0 *  64, 256), 256>>>(w[2],  p_Wp + OFF_E0U, DINR0, DINP0,  64);
    k_prep_W<<<cdiv(K_ * DINP1 * 128, 256), 256>>>(w[4],  p_Wp + OFF_E1G, DINR1, DINP1, 128);
    k_prep_W<<<cdiv(K_ * DINP1 *  64, 256), 256>>>(w[6],  p_Wp + OFF_E1U, DINR1, DINP1,  64);
    k_prep_W<<<cdiv(K_ * DINP0 * 128, 256), 256>>>(w[8],  p_Wp + OFF_D0G, DINR0, DINP0, 128);
    k_prep_W<<<cdiv(K_ * DINP0 *  64, 256), 256>>>(w[10], p_Wp + OFF_D0U, DINR0, DINP0,  64);
    k_prep_W<<<cdiv(K_ * DINP1 * 128, 256), 256>>>(w[12], p_Wp + OFF_D1G, DINR1, DINP1, 128);
    k_prep_W<<<cdiv(K_ * DINP1 *  64, 256), 256>>>(w[14], p_Wp + OFF_D1U, DINR1, DINP1,  64);

    // hoisted encoder x-products
    k_concat_xenc<<<cdiv(N_ * T_ * C_ * B_, 256), 256>>>();
    k_gemm1<<<dim3(LDE / 128, N_ / 128, 4), 256, G1_SMEM>>>(
        p_Gt, p_Xenc, p_Yx0, 0, LDE, nullptr);

    // ---------------- encoder, interleaved per timestep ----------------
    for (int t = 0; t < T_; t++) {
        const float* xt     = p_xT + (size_t)t * N_ * B_ * C_;
        const float* h0prev = (t == 0) ? nullptr : p_seq + (size_t)(t - 1) * NBH_;
        float* h0out        = p_seq + (size_t)t * NBH_;

        // layer 0 (x-prods hoisted; h-prods mirrored by prior enc1 gate)
        k_prep0e<<<cdiv(P0E_XPRODN + P0E_XCONCN, 256), 256>>>(t, xt, p_Y0,
                                                              p_X0);
        k_gemm2g<<<dim3(1, M_ / 128), 256>>>(p_X0, p_Y0, p_Wp + OFF_E0G, w[1],
                                             DINP0, h0prev, p_X0, C_);
        k_gemm1<<<dim3((H_ * B_) / 128, N_ / 128, 4), 256, G1_SMEM>>>(
            p_Gt, p_X0, p_Y0, C_ * B_, LDP0, nullptr);
        k_gemm2<<<dim3(1, M_ / 128), 256>>>(p_X0, p_Y0, p_Wp + OFF_E0U, w[3],
                                            DINP0, h0prev, h0out, p_X0, C_,
                                            p_X1);

        // layer 1 (gate gemm1 mirrors x-region into Y0 h-region)
        const float* h1prev = (t == 0) ? nullptr : p_hB;
        int gateCols = (t == 0) ? (H_ * B_) : (DINR1 * B_);
        k_gemm1<<<dim3(gateCols / 128, N_ / 128, 4), 256, G1_SMEM>>>(
            p_Gt, p_X1, p_Y1, 0, LDP1, p_Y0);
        k_gemm2g<<<dim3(1, M_ / 128), 256>>>(p_X1, p_Y1, p_Wp + OFF_E1G, w[5],
                                             DINP1, h1prev, p_X1, H_);
        k_gemm1<<<dim3((H_ * B_) / 128, N_ / 128, 4), 256, G1_SMEM>>>(
            p_Gt, p_X1, p_Y1, H_ * B_, LDP1, nullptr);
        k_gemm2<<<dim3(1, M_ / 128), 256>>>(p_X1, p_Y1, p_Wp + OFF_E1U, w[7],
                                            DINP1, h1prev, p_hB, p_X1, H_,
                                            nullptr);
    }

    // decoder t=0: X0 x-cols = 0 (g_y is zero)
    k_conc0<<<cdiv(N_ * C_ * B_, 256), 256>>>(p_y, p_X0);

    // ---------------- decoder ----------------
    for (int t = 0; t < HOR_; t++) {
        const float* h0prev = (t == 0) ? (p_seq + (size_t)(T_ - 1) * NBH_)
                                       : p_hA;

        // layer 0 (X0 x-cols from gemm2p; Y0 h-region from dec1/enc1 mirror)
        k_gemm1<<<dim3(1, N_ / 128, 4), 256, G1_SMEM>>>(p_Gt, p_X0, p_Y0,
                                                        0, LDP0, nullptr);
        k_gemm2g<<<dim3(1, M_ / 128), 256>>>(p_X0, p_Y0, p_Wp + OFF_D0G, w[9],
                                             DINP0, h0prev, p_X0, C_);
        k_gemm1<<<dim3((H_ * B_) / 128, N_ / 128, 4), 256, G1_SMEM>>>(
            p_Gt, p_X0, p_Y0, C_ * B_, LDP0, nullptr);
        k_gemm2<<<dim3(1, M_ / 128), 256>>>(p_X0, p_Y0, p_Wp + OFF_D0U, w[11],
                                            DINP0, h0prev, p_hA, p_X0, C_,
                                            p_X1);

        // layer 1 (gate gemm1 mirrors into Y0; update+proj writes X0 x-cols)
        k_gemm1<<<dim3((DINR1 * B_) / 128, N_ / 128, 4), 256, G1_SMEM>>>(
            p_Gt, p_X1, p_Y1, 0, LDP1, p_Y0);
        k_gemm2g<<<dim3(1, M_ / 128), 256>>>(p_X1, p_Y1, p_Wp + OFF_D1G, w[13],
                                             DINP1, p_hB, p_X1, H_);
        k_gemm1<<<dim3((H_ * B_) / 128, N_ / 128, 4), 256, G1_SMEM>>>(
            p_Gt, p_X1, p_Y1, H_ * B_, LDP1, nullptr);
        k_gemm2p<<<dim3(1, M_ / 128), 256, G2P_SMEM>>>(
            p_X1, p_Y1, p_Wp + OFF_D1U, w[15], p_hB, p_hB, p_X1, p_X0,
            projW, projb, t, out);
    }
}